// round 4
// baseline (speedup 1.0000x reference)
#include <cuda_runtime.h>
#include <math.h>

// ---- problem constants ----
#define NC    32      // hidden states C
#define NL    4       // fanout L
#define NM    128     // labels M
#define NDEPTH 7
#define NDIM  21845   // total nodes
#define NINT  5461    // internal nodes (= start of leaf level)
#define NLEAF 16384
#define JL    128     // C*L columns of A_SP
#define PAD   33      // shared stride (conflict-free both access patterns)

// ---- device scratch (no allocations allowed) ----
__device__ float  g_AS [JL * NC];   // [ (j*4+l) * 32 + i ] = smA[i,j,l]*smSP[l]
__device__ float  g_ASW[JL * NC];   // AS * (log smA + log smSP)
__device__ float  g_smB [NC * NM];  // [c*128 + m]
__device__ float  g_logB[NC * NM];
__device__ float  g_smPi [NC * NL]; // [c*4 + l]
__device__ float  g_logPi[NC * NL];
__device__ float  g_beta [NDIM * NC];
__device__ float  g_tbeta[NINT * NC];
__device__ float  g_eps  [NDIM * NC];
__device__ double g_ll;

__device__ __forceinline__ float wsum(float v) {
    #pragma unroll
    for (int o = 16; o; o >>= 1) v += __shfl_xor_sync(0xffffffffu, v, o);
    return v;
}
__device__ __forceinline__ float wmax(float v) {
    #pragma unroll
    for (int o = 16; o; o >>= 1) v = fmaxf(v, __shfl_xor_sync(0xffffffffu, v, o));
    return v;
}

// ---------------------------------------------------------------------------
// K0: softmaxes + derived tables + zero accumulator. One block, 256 threads.
// ---------------------------------------------------------------------------
__global__ void prep_kernel(const float* __restrict__ A,
                            const float* __restrict__ B,
                            const float* __restrict__ Pi,
                            const float* __restrict__ SP) {
    const int tid  = threadIdx.x;
    const int lane = tid & 31;
    const int warp = tid >> 5;
    const int nw   = blockDim.x >> 5;

    // smSP / logSP (L=4) — computed redundantly per thread
    float sp[NL], lsp[NL], smsp[NL];
    #pragma unroll
    for (int l = 0; l < NL; l++) sp[l] = SP[l];
    float mx = fmaxf(fmaxf(sp[0], sp[1]), fmaxf(sp[2], sp[3]));
    float ssum = 0.f;
    #pragma unroll
    for (int l = 0; l < NL; l++) ssum += expf(sp[l] - mx);
    float lse = logf(ssum) + mx;
    #pragma unroll
    for (int l = 0; l < NL; l++) { lsp[l] = sp[l] - lse; smsp[l] = expf(lsp[l]); }

    // smA over axis i (=lane), one warp per column (j,l)
    for (int col = warp; col < JL; col += nw) {
        const int l = col & 3;
        float a = A[lane * JL + col];          // A[i][j][l]
        float m = wmax(a);
        float e = expf(a - m);
        float s = wsum(e);
        float lsm = a - m - logf(s);
        float smv = e / s;
        float as  = smv * smsp[l];
        g_AS [col * NC + lane] = as;
        g_ASW[col * NC + lane] = as * (lsm + lsp[l]);
    }

    // smB over axis m, one warp per row c; lane holds 4 columns
    for (int c = warp; c < NC; c += nw) {
        float v[4];
        #pragma unroll
        for (int k = 0; k < 4; k++) v[k] = B[c * NM + lane + 32 * k];
        float m = fmaxf(fmaxf(v[0], v[1]), fmaxf(v[2], v[3]));
        m = wmax(m);
        float s = 0.f;
        #pragma unroll
        for (int k = 0; k < 4; k++) s += expf(v[k] - m);
        s = wsum(s);
        float l2 = logf(s) + m;
        #pragma unroll
        for (int k = 0; k < 4; k++) {
            float lsm = v[k] - l2;
            g_smB [c * NM + lane + 32 * k] = expf(lsm);
            g_logB[c * NM + lane + 32 * k] = lsm;
        }
    }

    // smPi over axis c (=lane), warp l handles column l
    if (warp < NL) {
        float p = Pi[lane * NL + warp];
        float m = wmax(p);
        float e = expf(p - m);
        float s = wsum(e);
        float lsm = p - m - logf(s);
        g_smPi [lane * NL + warp] = e / s;
        g_logPi[lane * NL + warp] = lsm;
    }

    if (tid == 0) g_ll = 0.0;
}

// ---------------------------------------------------------------------------
// K1: leaf beta init. One warp per leaf (lane = state c).
// ---------------------------------------------------------------------------
__global__ void leaf_kernel(const int* __restrict__ labels) {
    const int gw   = (blockIdx.x * blockDim.x + threadIdx.x) >> 5;
    const int lane = threadIdx.x & 31;
    if (gw >= NLEAF) return;
    const int node = NINT + gw;
    const int pos  = gw & 3;
    const int lab  = labels[node];
    float v = g_smPi[lane * NL + pos] * g_smB[lane * NM + lab];
    float s = wsum(v);
    g_beta[node * NC + lane] = v / s;
}

// ---------------------------------------------------------------------------
// K2..K8: upward level. One warp per parent (lane = state i).
// tb[i] = sum_{j,l} AS[(j,l),i] * beta_child[l][j]
// ---------------------------------------------------------------------------
__global__ void up_kernel(const int* __restrict__ labels,
                          int s_p, int n_p, int s_c) {
    __shared__ float AS[JL * PAD];
    const int tid  = threadIdx.x;
    const int lane = tid & 31;
    const int warp = tid >> 5;
    for (int k = tid; k < JL * NC; k += blockDim.x)
        AS[(k >> 5) * PAD + (k & 31)] = g_AS[k];
    __syncthreads();

    const int p = blockIdx.x * (blockDim.x >> 5) + warp;
    if (p >= n_p) return;
    const int node   = s_p + p;
    const int chbase = s_c + p * NL;

    float bv[NL];
    #pragma unroll
    for (int l = 0; l < NL; l++)
        bv[l] = g_beta[(chbase + l) * NC + lane];   // beta_child[l][lane]

    float tb = 0.f;
    #pragma unroll
    for (int j = 0; j < NC; j++) {
        #pragma unroll
        for (int l = 0; l < NL; l++) {
            float b = __shfl_sync(0xffffffffu, bv[l], j);
            tb = fmaf(AS[(j * NL + l) * PAD + lane], b, tb);
        }
    }
    g_tbeta[node * NC + lane] = tb;

    const int lab = labels[node];
    float bl = tb * g_smB[lane * NM + lab];
    float s  = wsum(bl);
    g_beta[node * NC + lane] = bl / s;
}

// ---------------------------------------------------------------------------
// K9..K15: downward level. One warp per parent.
//   r[i]   = eps_pa[i] / tbeta_pa[i]
//   s[j,l] = sum_i AS [(j,l),i] * r[i]   -> eps_child[l][j] = s*beta_child[l][j]
//   w[j,l] = sum_i ASW[(j,l),i] * r[i]   -> ll += beta_child[l][j]*w[j,l]
// Lane owns jl = lane + 32k, k=0..3.
// ---------------------------------------------------------------------------
__global__ void down_kernel(const int* __restrict__ labels,
                            int s_p, int n_p, int s_c,
                            int is_root, int is_leaf) {
    __shared__ float  AS [JL * PAD];
    __shared__ float  ASW[JL * PAD];
    __shared__ double blk_ll;
    const int tid  = threadIdx.x;
    const int lane = tid & 31;
    const int warp = tid >> 5;
    if (tid == 0) blk_ll = 0.0;
    for (int k = tid; k < JL * NC; k += blockDim.x) {
        AS [(k >> 5) * PAD + (k & 31)] = g_AS [k];
        ASW[(k >> 5) * PAD + (k & 31)] = g_ASW[k];
    }
    __syncthreads();

    const int p = blockIdx.x * (blockDim.x >> 5) + warp;
    float contrib = 0.f;
    if (p < n_p) {
        const int node = s_p + p;
        float epsv = is_root ? g_beta[lane]            // eps[0] = beta[0]
                             : g_eps[node * NC + lane];
        float r = epsv / g_tbeta[node * NC + lane];

        float sacc[4] = {0.f, 0.f, 0.f, 0.f};
        float wacc[4] = {0.f, 0.f, 0.f, 0.f};
        #pragma unroll
        for (int i = 0; i < NC; i++) {
            float ri = __shfl_sync(0xffffffffu, r, i);
            #pragma unroll
            for (int k = 0; k < 4; k++) {
                int jl = lane + 32 * k;
                sacc[k] = fmaf(AS [jl * PAD + i], ri, sacc[k]);
                wacc[k] = fmaf(ASW[jl * PAD + i], ri, wacc[k]);
            }
        }

        const int chbase = s_c + p * NL;
        #pragma unroll
        for (int k = 0; k < 4; k++) {
            int jl = lane + 32 * k;
            int j  = jl >> 2;
            int l  = jl & 3;
            int child = chbase + l;
            float b  = g_beta[child * NC + j];
            float ev = sacc[k] * b;
            g_eps[child * NC + j] = ev;
            int clab = labels[child];
            contrib += b * wacc[k];                      // t_eps*(logA+logSP)
            contrib += ev * g_logB[j * NM + clab];       // eps*logB (child)
            if (is_leaf) contrib += ev * g_logPi[j * NL + l];  // leaf eps*logPi
        }
        if (is_root) {
            int rlab = labels[0];
            contrib += g_beta[lane] * g_logB[lane * NM + rlab];  // root eps*logB
        }
    }
    contrib = wsum(contrib);
    if (lane == 0 && contrib != 0.f) atomicAdd(&blk_ll, (double)contrib);
    __syncthreads();
    if (tid == 0) atomicAdd(&g_ll, blk_ll);
}

// ---------------------------------------------------------------------------
// K16: write scalar output
// ---------------------------------------------------------------------------
__global__ void fin_kernel(float* __restrict__ out) {
    out[0] = (float)g_ll;
}

extern "C" void kernel_launch(void* const* d_in, const int* in_sizes, int n_in,
                              void* d_out, int out_size) {
    const int*   labels = (const int*)  d_in[0];
    const float* A      = (const float*)d_in[1];
    const float* B      = (const float*)d_in[2];
    const float* Pi     = (const float*)d_in[3];
    const float* SP     = (const float*)d_in[4];

    static const int starts[9] = {0, 1, 5, 21, 85, 341, 1365, 5461, 21845};

    prep_kernel<<<1, 256>>>(A, B, Pi, SP);
    leaf_kernel<<<(NLEAF * 32 + 255) / 256, 256>>>(labels);

    for (int d = NDEPTH - 1; d >= 0; --d) {
        int np = starts[d + 1] - starts[d];
        up_kernel<<<(np + 7) / 8, 256>>>(labels, starts[d], np, starts[d + 1]);
    }
    for (int d = 0; d < NDEPTH; ++d) {
        int np = starts[d + 1] - starts[d];
        down_kernel<<<(np + 7) / 8, 256>>>(labels, starts[d], np, starts[d + 1],
                                           d == 0 ? 1 : 0,
                                           d == NDEPTH - 1 ? 1 : 0);
    }
    fin_kernel<<<1, 1>>>((float*)d_out);
}

// round 5
// speedup vs baseline: 1.0283x; 1.0283x over previous
#include <cuda_runtime.h>
#include <math.h>

// ---- problem constants ----
#define NC 32
#define NL 4
#define NM 128
#define NBLK 148          // <= 152 SMs on GB300 -> all blocks co-resident
#define NTHR 1024

// table offsets (floats) inside the shared/global table blob
#define OFF_ASU    0      // [ (j*4+l)*33 + i ]           up layout, padded
#define OFF_ASD    4224   // [ i*132 + (j*4+l) ]          down layout (float4 rows)
#define OFF_ASWD   8448   // same layout as ASD
#define OFF_SMBT   12672  // [ m*32 + c ]
#define OFF_LOGBT  16768  // [ m*32 + c ]
#define OFF_SMPIT  20864  // [ l*32 + c ]
#define OFF_LOGPIT 20992  // [ l*32 + c ]
#define TABF       21120
#define SMEM_BYTES (TABF * 4)

// ---- device scratch ----
__device__ float  g_tab[TABF];
__device__ float  g_beta [21845 * NC];
__device__ float  g_tbeta[5461 * NC];
__device__ float  g_eps  [5461 * NC];     // internal nodes only
__device__ double g_ll;
__device__ unsigned int g_bar_count = 0;
__device__ unsigned int g_bar_gen   = 0;

__device__ __forceinline__ float wsum(float v) {
    #pragma unroll
    for (int o = 16; o; o >>= 1) v += __shfl_xor_sync(0xffffffffu, v, o);
    return v;
}
__device__ __forceinline__ float wmax(float v) {
    #pragma unroll
    for (int o = 16; o; o >>= 1) v = fmaxf(v, __shfl_xor_sync(0xffffffffu, v, o));
    return v;
}

// sense-reversing grid barrier (all NBLK blocks co-resident by construction)
__device__ __forceinline__ void grid_sync() {
    __syncthreads();
    if (threadIdx.x == 0) {
        __threadfence();
        volatile unsigned int* vg = &g_bar_gen;
        unsigned int old = *vg;
        if (atomicAdd(&g_bar_count, 1u) == NBLK - 1u) {
            atomicExch(&g_bar_count, 0u);
            __threadfence();
            atomicAdd(&g_bar_gen, 1u);
        } else {
            while (*vg == old) __nanosleep(64);
        }
        __threadfence();
    }
    __syncthreads();
}

// ---------------------------------------------------------------------------
// up level (generic): one warp per parent, lane = state i
// tb[i] = sum_{j,l} AS[(j,l),i] * beta_child[l][j]
// ---------------------------------------------------------------------------
__device__ __forceinline__ void up_level(int s_p, int n_p, int s_c,
        const int* __restrict__ labels, const float* __restrict__ ASu,
        const float* __restrict__ smBt, int gw, int nw, int lane)
{
    for (int p = gw; p < n_p; p += nw) {
        const int node = s_p + p, chbase = s_c + p * NL;
        float bv[NL];
        #pragma unroll
        for (int l = 0; l < NL; l++) bv[l] = g_beta[(chbase + l) * NC + lane];
        float tba[NL] = {0.f, 0.f, 0.f, 0.f};
        #pragma unroll
        for (int j = 0; j < NC; j++) {
            #pragma unroll
            for (int l = 0; l < NL; l++) {
                float b = __shfl_sync(0xffffffffu, bv[l], j);
                tba[l] = fmaf(ASu[(j * NL + l) * 33 + lane], b, tba[l]);
            }
        }
        float tb = (tba[0] + tba[1]) + (tba[2] + tba[3]);
        g_tbeta[node * NC + lane] = tb;
        float bl = tb * smBt[labels[node] * NC + lane];
        g_beta[node * NC + lane] = bl / wsum(bl);
    }
}

// up level d=6: children are leaves, compute their betas in-register
__device__ __forceinline__ void up_leaf(const int* __restrict__ labels,
        const float* __restrict__ ASu, const float* __restrict__ smBt,
        const float* __restrict__ smPit, int gw, int nw, int lane)
{
    for (int p = gw; p < 4096; p += nw) {
        const int node = 1365 + p, chbase = 5461 + p * NL;
        float bv[NL];
        #pragma unroll
        for (int l = 0; l < NL; l++) {
            const int child = chbase + l;
            float v = smPit[l * NC + lane] * smBt[labels[child] * NC + lane];
            v = v / wsum(v);
            bv[l] = v;
            g_beta[child * NC + lane] = v;
        }
        float tba[NL] = {0.f, 0.f, 0.f, 0.f};
        #pragma unroll
        for (int j = 0; j < NC; j++) {
            #pragma unroll
            for (int l = 0; l < NL; l++) {
                float b = __shfl_sync(0xffffffffu, bv[l], j);
                tba[l] = fmaf(ASu[(j * NL + l) * 33 + lane], b, tba[l]);
            }
        }
        float tb = (tba[0] + tba[1]) + (tba[2] + tba[3]);
        g_tbeta[node * NC + lane] = tb;
        float bl = tb * smBt[labels[node] * NC + lane];
        g_beta[node * NC + lane] = bl / wsum(bl);
    }
}

// ---------------------------------------------------------------------------
// down level: one warp per parent. lane = state i for r; lane = j for outputs.
//   r[i]   = eps_pa[i] / tbeta_pa[i]
//   s[j,l] = sum_i AS [(j,l),i] r[i] ; eps_child[l][j] = s*beta_child[l][j]
//   w[j,l] = sum_i ASW[(j,l),i] r[i] ; ll += beta_child[l][j]*w[j,l] + ...
// ---------------------------------------------------------------------------
__device__ __forceinline__ void down_level(int s_p, int n_p, int s_c,
        const int* __restrict__ labels,
        const float4* __restrict__ ASd, const float4* __restrict__ ASWd,
        const float* __restrict__ logBt, const float* __restrict__ logPit,
        int is_root, int is_leaf, int gw, int nw, int lane, float& acc)
{
    for (int p = gw; p < n_p; p += nw) {
        const int node = s_p + p;
        float epsv = is_root ? g_beta[lane] : g_eps[node * NC + lane];
        float r = epsv / g_tbeta[node * NC + lane];
        float4 sa = {0.f, 0.f, 0.f, 0.f}, wa = {0.f, 0.f, 0.f, 0.f};
        #pragma unroll
        for (int i = 0; i < NC; i++) {
            float ri = __shfl_sync(0xffffffffu, r, i);
            float4 a = ASd [i * 33 + lane];
            float4 w = ASWd[i * 33 + lane];
            sa.x = fmaf(a.x, ri, sa.x); sa.y = fmaf(a.y, ri, sa.y);
            sa.z = fmaf(a.z, ri, sa.z); sa.w = fmaf(a.w, ri, sa.w);
            wa.x = fmaf(w.x, ri, wa.x); wa.y = fmaf(w.y, ri, wa.y);
            wa.z = fmaf(w.z, ri, wa.z); wa.w = fmaf(w.w, ri, wa.w);
        }
        const int chbase = s_c + p * NL;
        float sl[NL] = {sa.x, sa.y, sa.z, sa.w};
        float wl[NL] = {wa.x, wa.y, wa.z, wa.w};
        #pragma unroll
        for (int l = 0; l < NL; l++) {
            const int child = chbase + l;
            float b  = g_beta[child * NC + lane];      // lane = j, coalesced
            float ev = sl[l] * b;
            if (!is_leaf) g_eps[child * NC + lane] = ev;
            const int clab = labels[child];            // warp-uniform
            acc += b * wl[l] + ev * logBt[clab * NC + lane];
            if (is_leaf) acc += ev * logPit[l * NC + lane];
        }
        if (is_root) acc += g_beta[lane] * logBt[labels[0] * NC + lane];
    }
}

// ---------------------------------------------------------------------------
// the single fused kernel
// ---------------------------------------------------------------------------
__global__ void __launch_bounds__(NTHR, 1) fused_kernel(
        const int* __restrict__ labels, const float* __restrict__ A,
        const float* __restrict__ B, const float* __restrict__ Pi,
        const float* __restrict__ SP, float* __restrict__ out)
{
    extern __shared__ float sh[];
    __shared__ double blk_ll;
    const int tid  = threadIdx.x;
    const int lane = tid & 31;
    const int warp = tid >> 5;
    const int gw   = (blockIdx.x * NTHR + tid) >> 5;
    const int nw   = (NBLK * NTHR) >> 5;     // 4736 warps

    if (tid == 0) blk_ll = 0.0;
    if (blockIdx.x == 0 && tid == 0) g_ll = 0.0;

    // ---- phase 0: distributed prep into g_tab ----
    if (gw < 128) {
        // softmax of SP (redundant, tiny)
        float sp[NL], lsp[NL], smsp[NL];
        #pragma unroll
        for (int l = 0; l < NL; l++) sp[l] = SP[l];
        float mx = fmaxf(fmaxf(sp[0], sp[1]), fmaxf(sp[2], sp[3]));
        float ssum = 0.f;
        #pragma unroll
        for (int l = 0; l < NL; l++) ssum += expf(sp[l] - mx);
        float lse = logf(ssum) + mx;
        #pragma unroll
        for (int l = 0; l < NL; l++) { lsp[l] = sp[l] - lse; smsp[l] = expf(lsp[l]); }

        const int col = gw, l = col & 3;
        float a = A[lane * 128 + col];             // A[i][j][l], lane = i
        float m = wmax(a);
        float e = expf(a - m);
        float s = wsum(e);
        float lsm = a - m - logf(s);
        float as  = (e / s) * smsp[l];
        g_tab[OFF_ASU  + col * 33 + lane]  = as;
        g_tab[OFF_ASD  + lane * 132 + col] = as;
        g_tab[OFF_ASWD + lane * 132 + col] = as * (lsm + lsp[l]);
    } else if (gw < 160) {
        const int c = gw - 128;
        float v[4];
        #pragma unroll
        for (int k = 0; k < 4; k++) v[k] = B[c * NM + lane + 32 * k];
        float m = fmaxf(fmaxf(v[0], v[1]), fmaxf(v[2], v[3]));
        m = wmax(m);
        float s = 0.f;
        #pragma unroll
        for (int k = 0; k < 4; k++) s += expf(v[k] - m);
        s = wsum(s);
        float l2 = logf(s) + m;
        #pragma unroll
        for (int k = 0; k < 4; k++) {
            const int mm = lane + 32 * k;
            float lsm = v[k] - l2;
            g_tab[OFF_SMBT  + mm * NC + c] = expf(lsm);
            g_tab[OFF_LOGBT + mm * NC + c] = lsm;
        }
    } else if (gw < 164) {
        const int l = gw - 160;
        float pv = Pi[lane * NL + l];              // lane = c
        float m = wmax(pv);
        float e = expf(pv - m);
        float s = wsum(e);
        float lsm = pv - m - logf(s);
        g_tab[OFF_SMPIT  + l * NC + lane] = e / s;
        g_tab[OFF_LOGPIT + l * NC + lane] = lsm;
    }
    grid_sync();                                                   // 1

    // ---- copy tables to shared ----
    for (int k = tid; k < TABF; k += NTHR) sh[k] = g_tab[k];
    __syncthreads();
    const float*  ASu    = sh + OFF_ASU;
    const float4* ASd    = (const float4*)(sh + OFF_ASD);
    const float4* ASWd   = (const float4*)(sh + OFF_ASWD);
    const float*  smBt   = sh + OFF_SMBT;
    const float*  logBt  = sh + OFF_LOGBT;
    const float*  smPit  = sh + OFF_SMPIT;
    const float*  logPit = sh + OFF_LOGPIT;

    // ---- up sweep (big levels) ----
    up_leaf(labels, ASu, smBt, smPit, gw, nw, lane);               // d=6 (+leaf init)
    grid_sync();                                                   // 2
    up_level(341, 1024, 1365, labels, ASu, smBt, gw, nw, lane);    // d=5
    grid_sync();                                                   // 3
    up_level(85, 256, 341, labels, ASu, smBt, gw, nw, lane);       // d=4
    grid_sync();                                                   // 4

    // ---- small levels (up d=3..0 + down d=0..3), block 0 only ----
    float acc = 0.f;
    if (blockIdx.x == 0) {
        up_level(21, 64, 85, labels, ASu, smBt, warp, 32, lane); __syncthreads();
        up_level(5, 16, 21, labels, ASu, smBt, warp, 32, lane);  __syncthreads();
        up_level(1, 4, 5,   labels, ASu, smBt, warp, 32, lane);  __syncthreads();
        up_level(0, 1, 1,   labels, ASu, smBt, warp, 32, lane);  __syncthreads();
        down_level(0, 1, 1,   labels, ASd, ASWd, logBt, logPit, 1, 0, warp, 32, lane, acc); __syncthreads();
        down_level(1, 4, 5,   labels, ASd, ASWd, logBt, logPit, 0, 0, warp, 32, lane, acc); __syncthreads();
        down_level(5, 16, 21, labels, ASd, ASWd, logBt, logPit, 0, 0, warp, 32, lane, acc); __syncthreads();
        down_level(21, 64, 85, labels, ASd, ASWd, logBt, logPit, 0, 0, warp, 32, lane, acc);
    }
    grid_sync();                                                   // 5

    // ---- down sweep (big levels) ----
    down_level(85, 256, 341, labels, ASd, ASWd, logBt, logPit, 0, 0, gw, nw, lane, acc);
    grid_sync();                                                   // 6
    down_level(341, 1024, 1365, labels, ASd, ASWd, logBt, logPit, 0, 0, gw, nw, lane, acc);
    grid_sync();                                                   // 7
    down_level(1365, 4096, 5461, labels, ASd, ASWd, logBt, logPit, 0, 1, gw, nw, lane, acc);

    // ---- log-likelihood reduction ----
    acc = wsum(acc);
    if (lane == 0 && acc != 0.f) atomicAdd(&blk_ll, (double)acc);
    __syncthreads();
    if (tid == 0 && blk_ll != 0.0) atomicAdd(&g_ll, blk_ll);
    grid_sync();                                                   // 8
    if (blockIdx.x == 0 && tid == 0) out[0] = (float)g_ll;
}

extern "C" void kernel_launch(void* const* d_in, const int* in_sizes, int n_in,
                              void* d_out, int out_size) {
    const int*   labels = (const int*)  d_in[0];
    const float* A      = (const float*)d_in[1];
    const float* B      = (const float*)d_in[2];
    const float* Pi     = (const float*)d_in[3];
    const float* SP     = (const float*)d_in[4];

    cudaFuncSetAttribute(fused_kernel,
                         cudaFuncAttributeMaxDynamicSharedMemorySize, SMEM_BYTES);
    fused_kernel<<<NBLK, NTHR, SMEM_BYTES>>>(labels, A, B, Pi, SP, (float*)d_out);
}

// round 7
// speedup vs baseline: 1.1278x; 1.0968x over previous
#include <cuda_runtime.h>
#include <math.h>

// ---- problem constants ----
#define NC 32
#define NL 4
#define NM 128
#define NBLK 148          // <= SM count -> all blocks co-resident
#define NTHR 1024

// shared-memory float offsets
#define OFF_ASU    0        // [i][c2=l*32+j], row stride 132 (33 float4)
#define OFF_ASD    4224     // [i][jl=j*4+l], row stride 132
#define OFF_ASWD   8448     // same layout as ASD
#define OFF_SMBT   12672    // [m*33 + c]
#define OFF_LOGBT  16896    // [m*33 + c]
#define OFF_SMPIT  21120    // [l*32 + c]
#define OFF_LOGPIT 21248    // [l*32 + c]
#define OFF_STAGE  21376    // 32 warps x 128 floats
#define TABF       25472
#define SMEM_BYTES (TABF * 4)

// ---- device scratch ----
__device__ float  g_beta [21845 * NC];
__device__ float  g_tbeta[5461 * NC];
__device__ float  g_eps  [5461 * NC];
__device__ double g_ll;
__device__ unsigned int g_bar_count = 0;
__device__ unsigned int g_bar_gen   = 0;
__device__ unsigned int g_done      = 0;

__device__ __forceinline__ float wsum(float v) {
    #pragma unroll
    for (int o = 16; o; o >>= 1) v += __shfl_xor_sync(0xffffffffu, v, o);
    return v;
}
__device__ __forceinline__ float wmax(float v) {
    #pragma unroll
    for (int o = 16; o; o >>= 1) v = fmaxf(v, __shfl_xor_sync(0xffffffffu, v, o));
    return v;
}

__device__ __forceinline__ void grid_sync() {
    __syncthreads();
    if (threadIdx.x == 0) {
        __threadfence();
        volatile unsigned int* vg = &g_bar_gen;
        unsigned int old = *vg;
        if (atomicAdd(&g_bar_count, 1u) == NBLK - 1u) {
            atomicExch(&g_bar_count, 0u);
            __threadfence();
            atomicAdd(&g_bar_gen, 1u);
        } else {
            while (*vg == old) __nanosleep(32);
        }
        __threadfence();
    }
    __syncthreads();
}

// ---------------------------------------------------------------------------
// up level (generic, shfl-free): one warp per parent, lane = state i.
// tb[i] = sum_{c2} ASu[i][c2] * stage[c2],  stage[l*32+j] = beta_child[l][j]
// ---------------------------------------------------------------------------
__device__ __forceinline__ void up_level(int s_p, int n_p, int s_c,
        const int* __restrict__ labels, const float4* __restrict__ ASu4,
        const float* __restrict__ smBt, float* __restrict__ stg,
        int gw, int nw, int lane)
{
    const float4* arow = ASu4 + lane * 33;
    const float4* st4  = (const float4*)stg;
    for (int p = gw; p < n_p; p += nw) {
        const int node = s_p + p, ch = s_c + p * NL;
        float b0 = g_beta[(ch + 0) * NC + lane];
        float b1 = g_beta[(ch + 1) * NC + lane];
        float b2 = g_beta[(ch + 2) * NC + lane];
        float b3 = g_beta[(ch + 3) * NC + lane];
        const int lab = labels[node];
        __syncwarp();
        stg[      lane] = b0; stg[ 32 + lane] = b1;
        stg[ 64 + lane] = b2; stg[ 96 + lane] = b3;
        __syncwarp();
        float a0 = 0.f, a1 = 0.f, a2 = 0.f, a3 = 0.f;
        #pragma unroll
        for (int k = 0; k < 32; k++) {
            float4 a = arow[k];
            float4 b = st4[k];
            a0 = fmaf(a.x, b.x, a0); a1 = fmaf(a.y, b.y, a1);
            a2 = fmaf(a.z, b.z, a2); a3 = fmaf(a.w, b.w, a3);
        }
        float tb = (a0 + a1) + (a2 + a3);
        g_tbeta[node * NC + lane] = tb;
        float bl = tb * smBt[lab * 33 + lane];
        g_beta[node * NC + lane] = bl / wsum(bl);
    }
}

// up level d=6: children are leaves; compute their betas in-register/stage
__device__ __forceinline__ void up_leaf(const int* __restrict__ labels,
        const float4* __restrict__ ASu4, const float* __restrict__ smBt,
        const float* __restrict__ smPit, float* __restrict__ stg,
        int gw, int nw, int lane)
{
    const float4* arow = ASu4 + lane * 33;
    const float4* st4  = (const float4*)stg;
    for (int p = gw; p < 4096; p += nw) {
        const int node = 1365 + p, ch = 5461 + p * NL;
        __syncwarp();
        #pragma unroll
        for (int l = 0; l < NL; l++) {
            const int child = ch + l;
            float v = smPit[l * NC + lane] * smBt[labels[child] * 33 + lane];
            v = v / wsum(v);
            g_beta[child * NC + lane] = v;
            stg[l * 32 + lane] = v;
        }
        __syncwarp();
        float a0 = 0.f, a1 = 0.f, a2 = 0.f, a3 = 0.f;
        #pragma unroll
        for (int k = 0; k < 32; k++) {
            float4 a = arow[k];
            float4 b = st4[k];
            a0 = fmaf(a.x, b.x, a0); a1 = fmaf(a.y, b.y, a1);
            a2 = fmaf(a.z, b.z, a2); a3 = fmaf(a.w, b.w, a3);
        }
        float tb = (a0 + a1) + (a2 + a3);
        g_tbeta[node * NC + lane] = tb;
        float bl = tb * smBt[labels[node] * 33 + lane];
        g_beta[node * NC + lane] = bl / wsum(bl);
    }
}

// ---------------------------------------------------------------------------
// down level: one warp per parent. lane = i for r; lane = j for outputs.
// ---------------------------------------------------------------------------
__device__ __forceinline__ void down_level(int s_p, int n_p, int s_c,
        const int* __restrict__ labels,
        const float4* __restrict__ ASd4, const float4* __restrict__ ASWd4,
        const float* __restrict__ logBt, const float* __restrict__ logPit,
        int is_root, int is_leaf, int gw, int nw, int lane, float& acc)
{
    for (int p = gw; p < n_p; p += nw) {
        const int node = s_p + p;
        float epsv = is_root ? g_beta[lane] : g_eps[node * NC + lane];
        float r = epsv / g_tbeta[node * NC + lane];
        float4 sa = {0.f, 0.f, 0.f, 0.f}, wa = {0.f, 0.f, 0.f, 0.f};
        #pragma unroll
        for (int i = 0; i < NC; i++) {
            float ri = __shfl_sync(0xffffffffu, r, i);
            float4 a = ASd4 [i * 33 + lane];
            float4 w = ASWd4[i * 33 + lane];
            sa.x = fmaf(a.x, ri, sa.x); sa.y = fmaf(a.y, ri, sa.y);
            sa.z = fmaf(a.z, ri, sa.z); sa.w = fmaf(a.w, ri, sa.w);
            wa.x = fmaf(w.x, ri, wa.x); wa.y = fmaf(w.y, ri, wa.y);
            wa.z = fmaf(w.z, ri, wa.z); wa.w = fmaf(w.w, ri, wa.w);
        }
        const int chbase = s_c + p * NL;
        float sl[NL] = {sa.x, sa.y, sa.z, sa.w};
        float wl[NL] = {wa.x, wa.y, wa.z, wa.w};
        #pragma unroll
        for (int l = 0; l < NL; l++) {
            const int child = chbase + l;
            float b  = g_beta[child * NC + lane];      // lane = j
            float ev = sl[l] * b;
            if (!is_leaf) g_eps[child * NC + lane] = ev;
            const int clab = labels[child];
            acc += b * wl[l] + ev * logBt[clab * 33 + lane];
            if (is_leaf) acc += ev * logPit[l * NC + lane];
        }
        if (is_root) acc += g_beta[lane] * logBt[labels[0] * 33 + lane];
    }
}

// ---------------------------------------------------------------------------
// the single fused kernel
// ---------------------------------------------------------------------------
__global__ void __launch_bounds__(NTHR, 1) fused_kernel(
        const int* __restrict__ labels, const float* __restrict__ A,
        const float* __restrict__ B, const float* __restrict__ Pi,
        const float* __restrict__ SP, float* __restrict__ out)
{
    extern __shared__ float sh[];
    __shared__ double blk_ll;
    const int tid  = threadIdx.x;
    const int lane = tid & 31;
    const int warp = tid >> 5;
    const int gw   = (blockIdx.x * NTHR + tid) >> 5;
    const int nw   = (NBLK * NTHR) >> 5;     // 4736 warps

    if (tid == 0) blk_ll = 0.0;
    if (blockIdx.x == 0 && tid == 0) g_ll = 0.0;

    // ---- per-block table build (no global round-trip, no grid barrier) ----
    {
        // SP softmax (redundant per thread)
        float sp[NL], lsp[NL], smsp[NL];
        #pragma unroll
        for (int l = 0; l < NL; l++) sp[l] = SP[l];
        float mx = fmaxf(fmaxf(sp[0], sp[1]), fmaxf(sp[2], sp[3]));
        float ssum = 0.f;
        #pragma unroll
        for (int l = 0; l < NL; l++) ssum += expf(sp[l] - mx);
        float lse = logf(ssum) + mx;
        #pragma unroll
        for (int l = 0; l < NL; l++) { lsp[l] = sp[l] - lse; smsp[l] = expf(lsp[l]); }

        // A softmax over i (=lane); warp w -> columns 4w..4w+3
        float av[4];
        #pragma unroll
        for (int cc = 0; cc < 4; cc++) av[cc] = A[lane * 128 + warp * 4 + cc];
        #pragma unroll
        for (int cc = 0; cc < 4; cc++) {
            const int col = warp * 4 + cc;        // col = j*4 + l
            const int j = col >> 2, l = col & 3;
            float a = av[cc];
            float m = wmax(a);
            float e = expf(a - m);
            float s = wsum(e);
            float lsm = a - m - logf(s);
            float as  = (e / s) * smsp[l];
            sh[OFF_ASU  + lane * 132 + (l * 32 + j)] = as;
            sh[OFF_ASD  + lane * 132 + col]          = as;
            sh[OFF_ASWD + lane * 132 + col]          = as * (lsm + lsp[l]);
        }

        // B softmax over m; warp w -> row c=w
        {
            const int c = warp;
            float v[4];
            #pragma unroll
            for (int k = 0; k < 4; k++) v[k] = B[c * NM + lane + 32 * k];
            float m = fmaxf(fmaxf(v[0], v[1]), fmaxf(v[2], v[3]));
            m = wmax(m);
            float s = 0.f;
            #pragma unroll
            for (int k = 0; k < 4; k++) s += expf(v[k] - m);
            s = wsum(s);
            float l2 = logf(s) + m;
            #pragma unroll
            for (int k = 0; k < 4; k++) {
                const int mm = lane + 32 * k;
                float lsm = v[k] - l2;
                sh[OFF_SMBT  + mm * 33 + c] = expf(lsm);
                sh[OFF_LOGBT + mm * 33 + c] = lsm;
            }
        }

        // Pi softmax over c (=lane); warps 0..3 -> column l
        if (warp < NL) {
            const int l = warp;
            float pv = Pi[lane * NL + l];
            float m = wmax(pv);
            float e = expf(pv - m);
            float s = wsum(e);
            float lsm = pv - m - logf(s);
            sh[OFF_SMPIT  + l * NC + lane] = e / s;
            sh[OFF_LOGPIT + l * NC + lane] = lsm;
        }
    }
    __syncthreads();

    const float4* ASu4   = (const float4*)(sh + OFF_ASU);
    const float4* ASd4   = (const float4*)(sh + OFF_ASD);
    const float4* ASWd4  = (const float4*)(sh + OFF_ASWD);
    const float*  smBt   = sh + OFF_SMBT;
    const float*  logBt  = sh + OFF_LOGBT;
    const float*  smPit  = sh + OFF_SMPIT;
    const float*  logPit = sh + OFF_LOGPIT;
    float* stg = sh + OFF_STAGE + warp * 128;

    // ---- up sweep (big levels) ----
    up_leaf(labels, ASu4, smBt, smPit, stg, gw, nw, lane);             // d=6
    grid_sync();                                                        // 1
    up_level(341, 1024, 1365, labels, ASu4, smBt, stg, gw, nw, lane);  // d=5
    grid_sync();                                                        // 2
    up_level(85, 256, 341, labels, ASu4, smBt, stg, gw, nw, lane);     // d=4
    grid_sync();                                                        // 3

    // ---- small levels, block 0 only ----
    float acc = 0.f;
    if (blockIdx.x == 0) {
        up_level(21, 64, 85, labels, ASu4, smBt, stg, warp, 32, lane); __syncthreads();
        up_level(5, 16, 21, labels, ASu4, smBt, stg, warp, 32, lane);  __syncthreads();
        up_level(1, 4, 5,   labels, ASu4, smBt, stg, warp, 32, lane);  __syncthreads();
        up_level(0, 1, 1,   labels, ASu4, smBt, stg, warp, 32, lane);  __syncthreads();
        down_level(0, 1, 1,   labels, ASd4, ASWd4, logBt, logPit, 1, 0, warp, 32, lane, acc); __syncthreads();
        down_level(1, 4, 5,   labels, ASd4, ASWd4, logBt, logPit, 0, 0, warp, 32, lane, acc); __syncthreads();
        down_level(5, 16, 21, labels, ASd4, ASWd4, logBt, logPit, 0, 0, warp, 32, lane, acc); __syncthreads();
        down_level(21, 64, 85, labels, ASd4, ASWd4, logBt, logPit, 0, 0, warp, 32, lane, acc);
    }
    grid_sync();                                                        // 4

    // ---- down sweep (big levels) ----
    down_level(85, 256, 341, labels, ASd4, ASWd4, logBt, logPit, 0, 0, gw, nw, lane, acc);
    grid_sync();                                                        // 5
    down_level(341, 1024, 1365, labels, ASd4, ASWd4, logBt, logPit, 0, 0, gw, nw, lane, acc);
    grid_sync();                                                        // 6
    down_level(1365, 4096, 5461, labels, ASd4, ASWd4, logBt, logPit, 0, 1, gw, nw, lane, acc);

    // ---- final reduction: last block to finish writes the output ----
    acc = wsum(acc);
    if (lane == 0) atomicAdd(&blk_ll, (double)acc);
    __syncthreads();
    if (tid == 0) {
        atomicAdd(&g_ll, blk_ll);
        __threadfence();
        if (atomicAdd(&g_done, 1u) == NBLK - 1u) {
            double v = atomicAdd(&g_ll, 0.0);
            out[0] = (float)v;
            g_done = 0;
            __threadfence();
        }
    }
}

extern "C" void kernel_launch(void* const* d_in, const int* in_sizes, int n_in,
                              void* d_out, int out_size) {
    const int*   labels = (const int*)  d_in[0];
    const float* A      = (const float*)d_in[1];
    const float* B      = (const float*)d_in[2];
    const float* Pi     = (const float*)d_in[3];
    const float* SP     = (const float*)d_in[4];

    static int smem_set = 0;
    if (!smem_set) {
        cudaFuncSetAttribute(fused_kernel,
                             cudaFuncAttributeMaxDynamicSharedMemorySize, SMEM_BYTES);
        smem_set = 1;
    }
    fused_kernel<<<NBLK, NTHR, SMEM_BYTES>>>(labels, A, B, Pi, SP, (float*)d_out);
}

// round 12
// speedup vs baseline: 1.8165x; 1.6106x over previous
#include <cuda_runtime.h>
#include <math.h>

// ---- problem constants ----
#define NC 32
#define NBLK 128          // 128 blocks, 2 subtrees each, all co-resident
#define NTHR 1024

// ---- shared-memory float offsets ----
#define O_ASC   0         // AS  [i*132 + (l*32+j)]  (c2-order, both sweeps)
#define O_ASW   4224      // ASW [i*132 + (l*32+j)]
#define O_SMB   8448      // smB  [m*33 + c]
#define O_LGB   12672     // logB [m*36 + c]   (float4-aligned rows)
#define O_SPI   17280     // smPi [l*32 + c]
#define O_LPI   17408     // logPi[l*32 + c]
#define O_STG   17536     // stage: 16 warps x 128 (global-children cases only)
#define O_SBB   19584     // subtree beta : 2 x 84 rows x 32
#define O_SBT   24960     // subtree tbeta: 2 x 21 rows x 32
#define O_SBE   26304     // subtree eps  : 2 x 20 rows x 32
#define O_TPB   27584     // top beta : 21 rows x 32
#define O_TPT   28256     // top tbeta: 21 rows x 32
#define O_TPE   28928     // top eps  : 85 rows x 32
#define TABF    31648
#define SMEM_BYTES (TABF * 4)

// ---- device scratch (cross-block data only) ----
__device__ float  g_beta [341 * NC];   // nodes 0..340 (levels 0..4)
__device__ float  g_tbeta[85 * NC];    // nodes 0..84 (only L3 entries used)
__device__ float  g_eps  [256 * NC];   // level-4 nodes 85..340 -> (n-85)*32
__device__ double g_ll;
__device__ unsigned int g_bar_count = 0;
__device__ unsigned int g_bar_gen   = 0;
__device__ unsigned int g_done      = 0;

__device__ __forceinline__ float wsum(float v) {
    #pragma unroll
    for (int o = 16; o; o >>= 1) v += __shfl_xor_sync(0xffffffffu, v, o);
    return v;
}
__device__ __forceinline__ float wmax(float v) {
    #pragma unroll
    for (int o = 16; o; o >>= 1) v = fmaxf(v, __shfl_xor_sync(0xffffffffu, v, o));
    return v;
}

__device__ __forceinline__ void grid_sync() {
    __syncthreads();
    if (threadIdx.x == 0) {
        __threadfence();
        volatile unsigned int* vg = &g_bar_gen;
        unsigned int old = *vg;
        if (atomicAdd(&g_bar_count, 1u) == NBLK - 1u) {
            atomicExch(&g_bar_count, 0u);
            __threadfence();
            atomicAdd(&g_bar_gen, 1u);
        } else {
            while (*vg == old) __nanosleep(32);
        }
        __threadfence();
    }
    __syncthreads();
}

// ---------------------------------------------------------------------------
// up matvec: lane = state i.  tb[i] = sum_c2 AS[i][c2] * st[c2]
// st4 points at 128 consecutive floats = child betas in c2-order (smem or any)
// ---------------------------------------------------------------------------
__device__ __forceinline__ float up_matvec(const float4* __restrict__ ASc4,
                                           const float4* __restrict__ st4, int lane) {
    const float4* arow = ASc4 + lane * 33;
    float a0 = 0.f, a1 = 0.f, a2 = 0.f, a3 = 0.f;
    #pragma unroll
    for (int k = 0; k < 32; k++) {
        float4 a = arow[k];
        float4 b = st4[k];
        a0 = fmaf(a.x, b.x, a0); a1 = fmaf(a.y, b.y, a1);
        a2 = fmaf(a.z, b.z, a2); a3 = fmaf(a.w, b.w, a3);
    }
    return (a0 + a1) + (a2 + a3);
}

__device__ __forceinline__ void up_epi(float tb, int lab, const float* __restrict__ smBt,
        float* __restrict__ tbeta_row, float* __restrict__ beta_row, int lane) {
    tbeta_row[lane] = tb;
    float bl = tb * smBt[lab * 33 + lane];
    beta_row[lane] = bl / wsum(bl);
}

// ---------------------------------------------------------------------------
// down matvec: r per-lane (lane = i).  s/w quads over c2 = 4*lane..4*lane+3
// ---------------------------------------------------------------------------
__device__ __forceinline__ void down_matvec(float r,
        const float4* __restrict__ ASc4, const float4* __restrict__ ASW4,
        int lane, float4& s4, float4& w4) {
    s4 = make_float4(0.f, 0.f, 0.f, 0.f);
    w4 = make_float4(0.f, 0.f, 0.f, 0.f);
    #pragma unroll
    for (int i = 0; i < NC; i++) {
        float ri = __shfl_sync(0xffffffffu, r, i);
        float4 a = ASc4[i * 33 + lane];
        float4 w = ASW4[i * 33 + lane];
        s4.x = fmaf(a.x, ri, s4.x); s4.y = fmaf(a.y, ri, s4.y);
        s4.z = fmaf(a.z, ri, s4.z); s4.w = fmaf(a.w, ri, s4.w);
        w4.x = fmaf(w.x, ri, w4.x); w4.y = fmaf(w.y, ri, w4.y);
        w4.z = fmaf(w.z, ri, w4.z); w4.w = fmaf(w.w, ri, w4.w);
    }
}

// down epilogue: cbeta = base of child0's 32-float row (children contiguous);
// ceps (nullable) same layout; clab4 = labels + first_child.
__device__ __forceinline__ void down_epi(const float* __restrict__ cbeta,
        float* __restrict__ ceps, const int* __restrict__ clab4,
        const float* __restrict__ logBt, const float* __restrict__ logPit,
        float4 s4, float4 w4, int lane, float& acc) {
    const int l = lane >> 3, jb = (lane * 4) & 31;
    const float4 b = *(const float4*)(cbeta + l * 32 + jb);
    float4 ev = make_float4(s4.x * b.x, s4.y * b.y, s4.z * b.z, s4.w * b.w);
    if (ceps) *(float4*)(ceps + l * 32 + jb) = ev;
    const int lb = clab4[l];
    const float4 g = *(const float4*)(logBt + lb * 36 + jb);
    acc += b.x * w4.x + b.y * w4.y + b.z * w4.z + b.w * w4.w
         + ev.x * g.x + ev.y * g.y + ev.z * g.z + ev.w * g.w;
    if (logPit) {
        const float4 p = *(const float4*)(logPit + l * 32 + jb);
        acc += ev.x * p.x + ev.y * p.y + ev.z * p.z + ev.w * p.w;
    }
}

// ---------------------------------------------------------------------------
// the single fused kernel
// ---------------------------------------------------------------------------
__global__ void __launch_bounds__(NTHR, 1) fused_kernel(
        const int* __restrict__ labels, const float* __restrict__ A,
        const float* __restrict__ B, const float* __restrict__ Pi,
        const float* __restrict__ SP, float* __restrict__ out)
{
    extern __shared__ float sh[];
    __shared__ double blk_ll;
    const int tid  = threadIdx.x;
    const int lane = tid & 31;
    const int w    = tid >> 5;                 // warp in block (0..31)
    const int bid  = blockIdx.x;
    const int gw   = (bid * NTHR + tid) >> 5;  // global warp

    if (tid == 0) blk_ll = 0.0;
    if (bid == 0 && tid == 0) g_ll = 0.0;

    // ---- table build (per block, redundant) ----
    {
        float sp[4], lsp[4], smsp[4];
        #pragma unroll
        for (int l = 0; l < 4; l++) sp[l] = SP[l];
        float mx = fmaxf(fmaxf(sp[0], sp[1]), fmaxf(sp[2], sp[3]));
        float ssum = 0.f;
        #pragma unroll
        for (int l = 0; l < 4; l++) ssum += expf(sp[l] - mx);
        float lse = logf(ssum) + mx;
        #pragma unroll
        for (int l = 0; l < 4; l++) { lsp[l] = sp[l] - lse; smsp[l] = expf(lsp[l]); }

        // A softmax over i (=lane); warp w -> cols 4w..4w+3 (col = j*4+l)
        float av[4];
        #pragma unroll
        for (int cc = 0; cc < 4; cc++) av[cc] = A[lane * 128 + w * 4 + cc];
        #pragma unroll
        for (int cc = 0; cc < 4; cc++) {
            const int col = w * 4 + cc, j = col >> 2, l = col & 3;
            float a = av[cc];
            float m = wmax(a);
            float e = expf(a - m);
            float s = wsum(e);
            float lsm = a - m - logf(s);
            float as  = (e / s) * smsp[l];
            sh[O_ASC + lane * 132 + (l * 32 + j)] = as;
            sh[O_ASW + lane * 132 + (l * 32 + j)] = as * (lsm + lsp[l]);
        }
        // B softmax over m; warp w -> row c=w
        {
            const int c = w;
            float v[4];
            #pragma unroll
            for (int k = 0; k < 4; k++) v[k] = B[c * 128 + lane + 32 * k];
            float m = fmaxf(fmaxf(v[0], v[1]), fmaxf(v[2], v[3]));
            m = wmax(m);
            float s = 0.f;
            #pragma unroll
            for (int k = 0; k < 4; k++) s += expf(v[k] - m);
            s = wsum(s);
            float l2 = logf(s) + m;
            #pragma unroll
            for (int k = 0; k < 4; k++) {
                const int mm = lane + 32 * k;
                float lsm = v[k] - l2;
                sh[O_SMB + mm * 33 + c] = expf(lsm);
                sh[O_LGB + mm * 36 + c] = lsm;
            }
        }
        // Pi softmax over c (=lane); warps 0..3 -> column l
        if (w < 4) {
            float pv = Pi[lane * 4 + w];
            float m = wmax(pv);
            float e = expf(pv - m);
            float s = wsum(e);
            float lsm = pv - m - logf(s);
            sh[O_SPI + w * 32 + lane] = e / s;
            sh[O_LPI + w * 32 + lane] = lsm;
        }
    }
    __syncthreads();

    const float4* ASc4 = (const float4*)(sh + O_ASC);
    const float4* ASW4 = (const float4*)(sh + O_ASW);
    const float*  smBt = sh + O_SMB;
    const float*  lgBt = sh + O_LGB;
    const float*  sPit = sh + O_SPI;
    const float*  lPit = sh + O_LPI;

    // subtree-local arrays: t in {0,1}; rows: L5 q->q, L6 k->4+k, leaf e->20+e
    float* sbB0 = sh + O_SBB;            // [t*84 + row]*32
    float* sbT0 = sh + O_SBT;            // rows: root 0, L5 1+q, L6 5+k
    float* sbE0 = sh + O_SBE;            // rows: L5 q, L6 4+k
    float* topB = sh + O_TPB;            // nodes 0..20
    float* topT = sh + O_TPT;
    float* topE = sh + O_TPE;            // nodes 0..84

    // =========== P1: subtree up-sweep (in-block) ===========
    {   // L6 parents (+ leaf betas): 32 warps, warp -> (t = w>>4, k = w&15)
        const int t = w >> 4, k = w & 15;
        const int s = 2 * bid + t;
        const int h = 1365 + 16 * s + k;          // L6 node
        const int lf = 5461 + 64 * s + 4 * k;     // first leaf child
        float* sbB = sbB0 + t * 84 * 32;
        #pragma unroll
        for (int l = 0; l < 4; l++) {
            const int lab = labels[lf + l];
            float v = sPit[l * 32 + lane] * smBt[lab * 33 + lane];
            v = v / wsum(v);
            sbB[(20 + 4 * k + l) * 32 + lane] = v;
        }
        __syncwarp();
        float tb = up_matvec(ASc4, (const float4*)(sbB + (20 + 4 * k) * 32), lane);
        up_epi(tb, labels[h], smBt, sbT0 + (t * 21 + 5 + k) * 32,
               sbB + (4 + k) * 32, lane);
    }
    __syncthreads();
    if (w < 8) {   // L5 parents: (t = w>>2, q = w&3)
        const int t = w >> 2, q = w & 3;
        const int s = 2 * bid + t;
        const int g5 = 341 + 4 * s + q;
        float* sbB = sbB0 + t * 84 * 32;
        float tb = up_matvec(ASc4, (const float4*)(sbB + (4 + 4 * q) * 32), lane);
        up_epi(tb, labels[g5], smBt, sbT0 + (t * 21 + 1 + q) * 32,
               sbB + q * 32, lane);
    }
    __syncthreads();
    if (w < 2) {   // L4 roots: t = w
        const int t = w, s = 2 * bid + t;
        float* sbB = sbB0 + t * 84 * 32;
        float tb = up_matvec(ASc4, (const float4*)sbB, lane);
        up_epi(tb, labels[85 + s], smBt, sbT0 + (t * 21) * 32,
               g_beta + (85 + s) * 32, lane);      // root beta -> GLOBAL
    }
    grid_sync();                                                      // bar 1

    // =========== P2: up L3 (64 parents, grid-strided) ===========
    if (gw < 64) {
        const int p = gw, node = 21 + p, cb = 85 + 4 * p;
        float* stg = sh + O_STG + w * 128;
        #pragma unroll
        for (int l = 0; l < 4; l++)
            stg[l * 32 + lane] = g_beta[(cb + l) * 32 + lane];
        __syncwarp();
        float tb = up_matvec(ASc4, (const float4*)stg, lane);
        up_epi(tb, labels[node], smBt, g_tbeta + node * 32,
               g_beta + node * 32, lane);
    }
    grid_sync();                                                      // bar 2

    // =========== P3: redundant top (levels 0..2) + down L3 ===========
    float acc = 0.f, acc_top = 0.f;
    if (w < 16) {  // up L2: 16 parents, children = L3 betas (global)
        const int node = 5 + w, cb = 21 + 4 * w;
        float* stg = sh + O_STG + w * 128;
        #pragma unroll
        for (int l = 0; l < 4; l++)
            stg[l * 32 + lane] = g_beta[(cb + l) * 32 + lane];
        __syncwarp();
        float tb = up_matvec(ASc4, (const float4*)stg, lane);
        up_epi(tb, labels[node], smBt, topT + node * 32, topB + node * 32, lane);
    }
    __syncthreads();
    if (w < 4) {   // up L1
        const int node = 1 + w;
        float tb = up_matvec(ASc4, (const float4*)(topB + (5 + 4 * w) * 32), lane);
        up_epi(tb, labels[node], smBt, topT + node * 32, topB + node * 32, lane);
    }
    __syncthreads();
    if (w == 0) {  // up L0 (root)
        float tb = up_matvec(ASc4, (const float4*)(topB + 1 * 32), lane);
        up_epi(tb, labels[0], smBt, topT, topB, lane);
    }
    __syncthreads();
    if (w == 0) {  // down L0: eps_root = beta_root
        float r = topB[lane] / topT[lane];
        float4 s4, w4;
        down_matvec(r, ASc4, ASW4, lane, s4, w4);
        down_epi(topB + 32, topE + 32, labels + 1, lgBt, 0, s4, w4, lane, acc_top);
        acc_top += topB[lane] * lgBt[labels[0] * 36 + lane];   // root eps*logB
        topE[lane] = topB[lane];
    }
    __syncthreads();
    if (w < 4) {   // down L1: parents 1..4 -> eps nodes 5..20
        const int node = 1 + w;
        float r = topE[node * 32 + lane] / topT[node * 32 + lane];
        float4 s4, w4;
        down_matvec(r, ASc4, ASW4, lane, s4, w4);
        down_epi(topB + (5 + 4 * w) * 32, topE + (5 + 4 * w) * 32,
                 labels + 5 + 4 * w, lgBt, 0, s4, w4, lane, acc_top);
    }
    __syncthreads();
    if (w < 16) {  // down L2: parents 5..20 -> eps L3 (children beta from global)
        const int node = 5 + w, cb = 21 + 4 * w;
        float r = topE[node * 32 + lane] / topT[node * 32 + lane];
        float4 s4, w4;
        down_matvec(r, ASc4, ASW4, lane, s4, w4);
        down_epi(g_beta + cb * 32, topE + cb * 32, labels + cb,
                 lgBt, 0, s4, w4, lane, acc_top);
    }
    __syncthreads();
    if (bid == 0) acc += acc_top;          // top ll counted once
    if (gw < 64) { // down L3 (grid-strided, non-redundant): eps -> g_eps
        const int p = gw, node = 21 + p, cb = 85 + 4 * p;
        float r = topE[node * 32 + lane] / g_tbeta[node * 32 + lane];
        float4 s4, w4;
        down_matvec(r, ASc4, ASW4, lane, s4, w4);
        down_epi(g_beta + cb * 32, g_eps + 4 * p * 32, labels + cb,
                 lgBt, 0, s4, w4, lane, acc);
    }
    grid_sync();                                                      // bar 3

    // =========== P4: subtree down-sweep (in-block) ===========
    if (w < 2) {   // L4 roots
        const int t = w, s = 2 * bid + t;
        float* sbB = sbB0 + t * 84 * 32;
        float r = g_eps[s * 32 + lane] / sbT0[(t * 21) * 32 + lane];
        float4 s4, w4;
        down_matvec(r, ASc4, ASW4, lane, s4, w4);
        down_epi(sbB, sbE0 + t * 20 * 32, labels + 341 + 4 * s,
                 lgBt, 0, s4, w4, lane, acc);
    }
    __syncthreads();
    if (w < 8) {   // L5 parents
        const int t = w >> 2, q = w & 3;
        const int s = 2 * bid + t;
        float* sbB = sbB0 + t * 84 * 32;
        float* sbE = sbE0 + t * 20 * 32;
        float r = sbE[q * 32 + lane] / sbT0[(t * 21 + 1 + q) * 32 + lane];
        float4 s4, w4;
        down_matvec(r, ASc4, ASW4, lane, s4, w4);
        down_epi(sbB + (4 + 4 * q) * 32, sbE + (4 + 4 * q) * 32,
                 labels + 1365 + 16 * s + 4 * q, lgBt, 0, s4, w4, lane, acc);
    }
    __syncthreads();
    {              // L6 parents (leaf children, ll only)
        const int t = w >> 4, k = w & 15;
        const int s = 2 * bid + t;
        float* sbB = sbB0 + t * 84 * 32;
        float* sbE = sbE0 + t * 20 * 32;
        float r = sbE[(4 + k) * 32 + lane] / sbT0[(t * 21 + 5 + k) * 32 + lane];
        float4 s4, w4;
        down_matvec(r, ASc4, ASW4, lane, s4, w4);
        down_epi(sbB + (20 + 4 * k) * 32, 0, labels + 5461 + 64 * s + 4 * k,
                 lgBt, lPit, s4, w4, lane, acc);
    }

    // ---- final reduction: last block writes the output ----
    acc = wsum(acc);
    if (lane == 0) atomicAdd(&blk_ll, (double)acc);
    __syncthreads();
    if (tid == 0) {
        atomicAdd(&g_ll, blk_ll);
        __threadfence();
        if (atomicAdd(&g_done, 1u) == NBLK - 1u) {
            double v = atomicAdd(&g_ll, 0.0);
            out[0] = (float)v;
            g_done = 0;
            __threadfence();
        }
    }
}

extern "C" void kernel_launch(void* const* d_in, const int* in_sizes, int n_in,
                              void* d_out, int out_size) {
    const int*   labels = (const int*)  d_in[0];
    const float* A      = (const float*)d_in[1];
    const float* B      = (const float*)d_in[2];
    const float* Pi     = (const float*)d_in[3];
    const float* SP     = (const float*)d_in[4];

    static int smem_set = 0;
    if (!smem_set) {
        cudaFuncSetAttribute(fused_kernel,
                             cudaFuncAttributeMaxDynamicSharedMemorySize, SMEM_BYTES);
        smem_set = 1;
    }
    fused_kernel<<<NBLK, NTHR, SMEM_BYTES>>>(labels, A, B, Pi, SP, (float*)d_out);
}